// round 4
// baseline (speedup 1.0000x reference)
#include <cuda_runtime.h>
#include <math.h>

// ---------------- problem constants (fixed shapes) ----------------
#define T_TOK 1024
#define D_DIM 2048
#define E_NUM 64
#define F_DIM 768
#define TOPK  8
#define NA    (T_TOK * TOPK)     // 8192 assignments
#define TM    64                 // M-tile (rows per expert padded to this)
#define MAX_ROWS  12288          // >= 8192 + 64*63 = 12224
#define MAX_TILES 192            // >= 12224/64 = 191

// ---------------- device scratch (no allocations allowed) ----------------
__device__ int   d_counts[E_NUM];
__device__ int   d_cursor[E_NUM];
__device__ int   d_tile_expert[MAX_TILES];
__device__ int   d_ntiles;
__device__ int   d_perm[MAX_ROWS];          // padded row -> assignment idx (t*8+k), -1 = dummy
__device__ int   d_topk[NA];                // assignment -> expert
__device__ float d_wt[NA];                  // assignment -> combine weight
__device__ float d_gu[MAX_ROWS * 2 * F_DIM];// gemm1 output [rows,1536]
__device__ float d_h [MAX_ROWS * F_DIM];    // swiglu output [rows,768]

// ---------------- k0: zero expert counts ----------------
__global__ void zero_counts_kernel() {
    d_counts[threadIdx.x] = 0;
}

// ---------------- k1: router (one block per token) ----------------
// logits = x @ gate^T ; top-8 by logit; weights = softmax over the 8 selected
// logits (identical to softmax-then-topk-then-renormalize).
__global__ void router_kernel(const float* __restrict__ x,
                              const float* __restrict__ gate) {
    __shared__ float xs[D_DIM];
    __shared__ float slog[E_NUM];
    const int t = blockIdx.x;
    const int tid = threadIdx.x;

    const float4* xg  = (const float4*)(x + (size_t)t * D_DIM);
    float4* xs4 = (float4*)xs;
    xs4[tid]        = xg[tid];
    xs4[tid + 256]  = xg[tid + 256];
    __syncthreads();

    const int e   = tid >> 2;      // expert, 0..63
    const int sub = tid & 3;       // 4 threads per expert
    const float4* g4 = (const float4*)(gate + (size_t)e * D_DIM);
    float p = 0.f;
    #pragma unroll 4
    for (int j = sub; j < D_DIM / 4; j += 4) {
        float4 xv = xs4[j];
        float4 gv = g4[j];
        p += xv.x * gv.x + xv.y * gv.y + xv.z * gv.z + xv.w * gv.w;
    }
    p += __shfl_down_sync(0xffffffffu, p, 2, 4);
    p += __shfl_down_sync(0xffffffffu, p, 1, 4);
    if (sub == 0) slog[e] = p;
    __syncthreads();

    if (tid == 0) {
        float l[E_NUM];
        #pragma unroll
        for (int i = 0; i < E_NUM; i++) l[i] = slog[i];
        int   idx[TOPK];
        float val[TOPK];
        for (int k = 0; k < TOPK; k++) {
            int bi = 0; float bv = -1e30f;
            for (int i = 0; i < E_NUM; i++) {
                if (l[i] > bv) { bv = l[i]; bi = i; }
            }
            idx[k] = bi; val[k] = bv; l[bi] = -1e30f;
        }
        const float m = val[0];
        float w[TOPK], s = 0.f;
        for (int k = 0; k < TOPK; k++) { w[k] = __expf(val[k] - m); s += w[k]; }
        const float inv = 1.f / s;
        for (int k = 0; k < TOPK; k++) {
            d_topk[t * TOPK + k] = idx[k];
            d_wt  [t * TOPK + k] = w[k] * inv;
            atomicAdd(&d_counts[idx[k]], 1);
        }
    }
}

// ---------------- k2: build padded offsets / tile map / reset perm ----------------
__global__ void build_kernel() {
    const int tid = threadIdx.x;
    if (tid == 0) {
        int off = 0;
        for (int e = 0; e < E_NUM; e++) {
            d_cursor[e] = off;
            const int nt = (d_counts[e] + TM - 1) / TM;
            for (int j = 0; j < nt; j++) d_tile_expert[off / TM + j] = e;
            off += nt * TM;
        }
        d_ntiles = off / TM;
    }
    for (int i = tid; i < MAX_ROWS; i += blockDim.x) d_perm[i] = -1;
}

// ---------------- k3: scatter assignments into per-expert segments ----------------
__global__ void scatter_kernel() {
    const int i = blockIdx.x * blockDim.x + threadIdx.x;
    if (i < NA) {
        const int e   = d_topk[i];
        const int pos = atomicAdd(&d_cursor[e], 1);
        d_perm[pos] = i;
    }
}

// ---------------- k4: GEMM1  gu[r, 0:1536] = gather(x)[r,:] @ w13_e^T ----------------
// C[M,N] = A[M,K] * B[N,K]^T; K = 2048. 64x64x32 tiles, 256 threads, 4x4/thread.
__global__ void gemm1_kernel(const float* __restrict__ x,
                             const float* __restrict__ w13) {
    constexpr int BM = 64, BN = 64, BK = 32;
    __shared__ float As[BK][BM];   // k-major
    __shared__ float Bs[BK][BN];

    const int tile = blockIdx.y;
    if (tile >= d_ntiles) return;
    const int e    = d_tile_expert[tile];
    const int row0 = tile * BM;
    const int n0   = blockIdx.x * BN;
    const int tid  = threadIdx.x;

    const int lr = tid >> 2;          // load row 0..63
    const int lc = (tid & 3) * 8;     // load col offset 0/8/16/24
    const int a_idx = d_perm[row0 + lr];
    const float* ap = (a_idx >= 0)
        ? (x + (size_t)(a_idx >> 3) * D_DIM + lc) : nullptr;
    const float* bp = w13 + (size_t)e * (2 * F_DIM) * D_DIM
                          + (size_t)(n0 + lr) * D_DIM + lc;

    const int tm = (tid >> 4) * 4;    // 0..60
    const int tn = (tid & 15) * 4;    // 0..60
    float acc[4][4] = {};

    for (int k0 = 0; k0 < D_DIM; k0 += BK) {
        float4 a0 = make_float4(0.f, 0.f, 0.f, 0.f), a1 = a0;
        if (ap) {
            a0 = *(const float4*)(ap + k0);
            a1 = *(const float4*)(ap + k0 + 4);
        }
        const float4 b0 = *(const float4*)(bp + k0);
        const float4 b1 = *(const float4*)(bp + k0 + 4);
        __syncthreads();
        As[lc + 0][lr] = a0.x; As[lc + 1][lr] = a0.y;
        As[lc + 2][lr] = a0.z; As[lc + 3][lr] = a0.w;
        As[lc + 4][lr] = a1.x; As[lc + 5][lr] = a1.y;
        As[lc + 6][lr] = a1.z; As[lc + 7][lr] = a1.w;
        Bs[lc + 0][lr] = b0.x; Bs[lc + 1][lr] = b0.y;
        Bs[lc + 2][lr] = b0.z; Bs[lc + 3][lr] = b0.w;
        Bs[lc + 4][lr] = b1.x; Bs[lc + 5][lr] = b1.y;
        Bs[lc + 6][lr] = b1.z; Bs[lc + 7][lr] = b1.w;
        __syncthreads();
        #pragma unroll
        for (int kk = 0; kk < BK; kk++) {
            float a[4], b[4];
            *(float4*)a = *(const float4*)&As[kk][tm];
            *(float4*)b = *(const float4*)&Bs[kk][tn];
            #pragma unroll
            for (int i = 0; i < 4; i++)
                #pragma unroll
                for (int j = 0; j < 4; j++)
                    acc[i][j] = fmaf(a[i], b[j], acc[i][j]);
        }
    }
    #pragma unroll
    for (int i = 0; i < 4; i++) {
        float* gp = d_gu + (size_t)(row0 + tm + i) * (2 * F_DIM) + n0 + tn;
        *(float4*)gp = make_float4(acc[i][0], acc[i][1], acc[i][2], acc[i][3]);
    }
}

// ---------------- k5: swiglu  h = silu(gu[:, :768]) * gu[:, 768:] ----------------
__global__ void swiglu_kernel() {
    const int idx = blockIdx.x * 256 + threadIdx.x;
    const int r = idx / F_DIM;
    if (r >= d_ntiles * TM) return;
    const int f = idx - r * F_DIM;
    const float g = d_gu[(size_t)r * (2 * F_DIM) + f];
    const float u = d_gu[(size_t)r * (2 * F_DIM) + F_DIM + f];
    d_h[idx] = u * g / (1.f + __expf(-g));
}

// ---------------- k6: GEMM2  out[t,:] += wt * (h[r,:] @ w2_e^T) ----------------
// C[M,N] = A[M,K] * B[N,K]^T; K = 768, N = 2048.
__global__ void gemm2_kernel(const float* __restrict__ w2,
                             float* __restrict__ out) {
    constexpr int BM = 64, BN = 64, BK = 32;
    __shared__ float As[BK][BM];
    __shared__ float Bs[BK][BN];

    const int tile = blockIdx.y;
    if (tile >= d_ntiles) return;
    const int e    = d_tile_expert[tile];
    const int row0 = tile * BM;
    const int n0   = blockIdx.x * BN;
    const int tid  = threadIdx.x;

    const int lr = tid >> 2;
    const int lc = (tid & 3) * 8;
    const float* ap = d_h + (size_t)(row0 + lr) * F_DIM + lc;
    const float* bp = w2 + (size_t)e * D_DIM * F_DIM
                         + (size_t)(n0 + lr) * F_DIM + lc;

    const int tm = (tid >> 4) * 4;
    const int tn = (tid & 15) * 4;
    float acc[4][4] = {};

    for (int k0 = 0; k0 < F_DIM; k0 += BK) {
        const float4 a0 = *(const float4*)(ap + k0);
        const float4 a1 = *(const float4*)(ap + k0 + 4);
        const float4 b0 = *(const float4*)(bp + k0);
        const float4 b1 = *(const float4*)(bp + k0 + 4);
        __syncthreads();
        As[lc + 0][lr] = a0.x; As[lc + 1][lr] = a0.y;
        As[lc + 2][lr] = a0.z; As[lc + 3][lr] = a0.w;
        As[lc + 4][lr] = a1.x; As[lc + 5][lr] = a1.y;
        As[lc + 6][lr] = a1.z; As[lc + 7][lr] = a1.w;
        Bs[lc + 0][lr] = b0.x; Bs[lc + 1][lr] = b0.y;
        Bs[lc + 2][lr] = b0.z; Bs[lc + 3][lr] = b0.w;
        Bs[lc + 4][lr] = b1.x; Bs[lc + 5][lr] = b1.y;
        Bs[lc + 6][lr] = b1.z; Bs[lc + 7][lr] = b1.w;
        __syncthreads();
        #pragma unroll
        for (int kk = 0; kk < BK; kk++) {
            float a[4], b[4];
            *(float4*)a = *(const float4*)&As[kk][tm];
            *(float4*)b = *(const float4*)&Bs[kk][tn];
            #pragma unroll
            for (int i = 0; i < 4; i++)
                #pragma unroll
                for (int j = 0; j < 4; j++)
                    acc[i][j] = fmaf(a[i], b[j], acc[i][j]);
        }
    }
    #pragma unroll
    for (int i = 0; i < 4; i++) {
        const int a = d_perm[row0 + tm + i];
        if (a >= 0) {
            const int   t = a >> 3;
            const float w = d_wt[a];
            float* op = out + (size_t)t * D_DIM + n0 + tn;
            #pragma unroll
            for (int j = 0; j < 4; j++)
                atomicAdd(op + j, w * acc[i][j]);
        }
    }
}

// ---------------- launch ----------------
extern "C" void kernel_launch(void* const* d_in, const int* in_sizes, int n_in,
                              void* d_out, int out_size) {
    const float* x    = (const float*)d_in[0];
    const float* gate = (const float*)d_in[1];
    const float* w13  = (const float*)d_in[2];
    const float* w2   = (const float*)d_in[3];
    float* out = (float*)d_out;

    cudaMemsetAsync(d_out, 0, (size_t)T_TOK * D_DIM * sizeof(float));
    zero_counts_kernel<<<1, E_NUM>>>();
    router_kernel<<<T_TOK, 256>>>(x, gate);
    build_kernel<<<1, 256>>>();
    scatter_kernel<<<NA / 256, 256>>>();
    gemm1_kernel<<<dim3(2 * F_DIM / 64, MAX_TILES), 256>>>(x, w13);
    swiglu_kernel<<<(MAX_ROWS * F_DIM) / 256, 256>>>();
    gemm2_kernel<<<dim3(D_DIM / 64, MAX_TILES), 256>>>(w2, out);
}

// round 9
// speedup vs baseline: 2.5136x; 2.5136x over previous
#include <cuda_runtime.h>
#include <cuda_bf16.h>
#include <math.h>
#include <stdint.h>

// ---------------- problem constants ----------------
#define T_TOK 1024
#define D_DIM 2048
#define E_NUM 64
#define F_DIM 768
#define TOPK  8
#define NA    (T_TOK * TOPK)
#define TM    128
#define MAX_ROWS  16384           // >= 8192 + 64*127 = 16320
#define MAX_TILES 128

// ---------------- device scratch ----------------
__device__ int   d_counts[E_NUM];
__device__ int   d_cursor[E_NUM];
__device__ int   d_tile_expert[MAX_TILES];
__device__ int   d_ntiles;
__device__ int   d_perm[MAX_ROWS];
__device__ int   d_topk[NA];
__device__ float d_wt[NA];
__device__ __align__(16) __nv_bfloat16 d_h_hi[(size_t)MAX_ROWS * F_DIM];
__device__ __align__(16) __nv_bfloat16 d_h_lo[(size_t)MAX_ROWS * F_DIM];

// ---------------- warp-MMA helpers (base sm_103 ISA: ldmatrix + HMMA) -------
// smem tiles: rows of 32 bf16 (64B) = 4 chunks of 16B.
// swizzle: phys chunk = c ^ ((row>>1)&3)  -> conflict-free ldmatrix & STS.128
__device__ __forceinline__ uint32_t swz(int row, int c) {
    return (uint32_t)(row * 64 + ((c ^ ((row >> 1) & 3)) << 4));
}
__device__ __forceinline__ void ldsm4(uint32_t* r, uint32_t addr) {
    asm volatile("ldmatrix.sync.aligned.m8n8.x4.shared.b16 {%0,%1,%2,%3}, [%4];"
                 : "=r"(r[0]), "=r"(r[1]), "=r"(r[2]), "=r"(r[3]) : "r"(addr));
}
__device__ __forceinline__ void mma16816(float* c, const uint32_t* a, const uint32_t* b) {
    asm volatile(
        "mma.sync.aligned.m16n8k16.row.col.f32.bf16.bf16.f32 "
        "{%0,%1,%2,%3}, {%4,%5,%6,%7}, {%8,%9}, {%0,%1,%2,%3};"
        : "+f"(c[0]), "+f"(c[1]), "+f"(c[2]), "+f"(c[3])
        : "r"(a[0]), "r"(a[1]), "r"(a[2]), "r"(a[3]), "r"(b[0]), "r"(b[1]));
}
// fp32x8 -> bf16 hi (truncate) + bf16 lo (rn residual), 16B each
__device__ __forceinline__ void split8(float4 v0, float4 v1, uint4& hi, uint4& lo) {
    float f[8] = {v0.x, v0.y, v0.z, v0.w, v1.x, v1.y, v1.z, v1.w};
    uint32_t h[8]; float l[8];
    #pragma unroll
    for (int i = 0; i < 8; i++) {
        h[i] = __float_as_uint(f[i]) & 0xffff0000u;
        l[i] = f[i] - __uint_as_float(h[i]);
    }
    hi.x = (h[0] >> 16) | h[1]; hi.y = (h[2] >> 16) | h[3];
    hi.z = (h[4] >> 16) | h[5]; hi.w = (h[6] >> 16) | h[7];
    __nv_bfloat162 p;
    p = __floats2bfloat162_rn(l[0], l[1]); lo.x = *(uint32_t*)&p;
    p = __floats2bfloat162_rn(l[2], l[3]); lo.y = *(uint32_t*)&p;
    p = __floats2bfloat162_rn(l[4], l[5]); lo.z = *(uint32_t*)&p;
    p = __floats2bfloat162_rn(l[6], l[7]); lo.w = *(uint32_t*)&p;
}

// ---------------- k0..k3: routing (unchanged, measured negligible) ----------
__global__ void zero_counts_kernel() { d_counts[threadIdx.x] = 0; }

__global__ void router_kernel(const float* __restrict__ x,
                              const float* __restrict__ gate) {
    __shared__ float xs[D_DIM];
    __shared__ float slog[E_NUM];
    const int t = blockIdx.x;
    const int tid = threadIdx.x;
    const float4* xg = (const float4*)(x + (size_t)t * D_DIM);
    float4* xs4 = (float4*)xs;
    xs4[tid] = xg[tid];
    xs4[tid + 256] = xg[tid + 256];
    __syncthreads();
    const int e = tid >> 2, sub = tid & 3;
    const float4* g4 = (const float4*)(gate + (size_t)e * D_DIM);
    float p = 0.f;
    #pragma unroll 4
    for (int j = sub; j < D_DIM / 4; j += 4) {
        float4 xv = xs4[j], gv = g4[j];
        p += xv.x * gv.x + xv.y * gv.y + xv.z * gv.z + xv.w * gv.w;
    }
    p += __shfl_down_sync(0xffffffffu, p, 2, 4);
    p += __shfl_down_sync(0xffffffffu, p, 1, 4);
    if (sub == 0) slog[e] = p;
    __syncthreads();
    if (tid == 0) {
        float l[E_NUM];
        #pragma unroll
        for (int i = 0; i < E_NUM; i++) l[i] = slog[i];
        int idx[TOPK]; float val[TOPK];
        for (int k = 0; k < TOPK; k++) {
            int bi = 0; float bv = -1e30f;
            for (int i = 0; i < E_NUM; i++)
                if (l[i] > bv) { bv = l[i]; bi = i; }
            idx[k] = bi; val[k] = bv; l[bi] = -1e30f;
        }
        const float m = val[0];
        float w[TOPK], s = 0.f;
        for (int k = 0; k < TOPK; k++) { w[k] = __expf(val[k] - m); s += w[k]; }
        const float inv = 1.f / s;
        for (int k = 0; k < TOPK; k++) {
            d_topk[t * TOPK + k] = idx[k];
            d_wt  [t * TOPK + k] = w[k] * inv;
            atomicAdd(&d_counts[idx[k]], 1);
        }
    }
}

__global__ void build_kernel() {
    const int tid = threadIdx.x;
    if (tid == 0) {
        int off = 0;
        for (int e = 0; e < E_NUM; e++) {
            d_cursor[e] = off;
            const int nt = (d_counts[e] + TM - 1) / TM;
            for (int j = 0; j < nt; j++) d_tile_expert[off / TM + j] = e;
            off += nt * TM;
        }
        d_ntiles = off / TM;
    }
    for (int i = tid; i < MAX_ROWS; i += blockDim.x) d_perm[i] = -1;
}

__global__ void scatter_kernel() {
    const int i = blockIdx.x * blockDim.x + threadIdx.x;
    if (i < NA) {
        const int e = d_topk[i];
        const int pos = atomicAdd(&d_cursor[e], 1);
        d_perm[pos] = i;
    }
}

// ================ GEMM1 + fused SwiGLU (warp-MMA bf16 3-split) ===============
// CTA: 128 rows x (gate 128 | up 128), K=2048 in 64 chunks of 32.
// 512 thr / 16 warps (4x4), warp tile 32x64.
// stage: A_hi 8K | A_lo 8K | B_hi 16K | B_lo 16K = 48K, x2 = 96K; epilogue Cs 128K.
#define G1_STG  49152
#define G1_SMEM 131072

__global__ void __launch_bounds__(512, 1)
gemm1_kernel(const float* __restrict__ x, const float* __restrict__ w13) {
    const int tile = blockIdx.y;
    if (tile >= d_ntiles) return;
    extern __shared__ __align__(1024) char smem[];
    const int e    = d_tile_expert[tile];
    const int row0 = tile * TM;
    const int f0   = blockIdx.x * 128;
    const int tid  = threadIdx.x;
    const int lane = tid & 31;
    const int warp = tid >> 5;
    const int wm = warp & 3, wn = warp >> 2;
    uint32_t sb;
    asm("{ .reg .u64 t; cvta.to.shared.u64 t, %1; cvt.u32.u64 %0, t; }"
        : "=r"(sb) : "l"(smem));

    // global load mapping
    const int ar = tid >> 2, aseg = tid & 3;                // A: 128 rows x 4 chunks
    const int aidx = d_perm[row0 + ar];
    const float* ap = (aidx >= 0) ? (x + (size_t)(aidx >> 3) * D_DIM + aseg * 8) : nullptr;
    const uint32_t a_sw = swz(ar, aseg);
    const int brn = tid >> 1, bhalf = tid & 1;              // B: 256 rows x 2 halves
    const int brow = (brn < 128) ? (f0 + brn) : (F_DIM + f0 + brn - 128);
    const float* bp = w13 + (size_t)e * (2 * F_DIM) * D_DIM
                          + (size_t)brow * D_DIM + bhalf * 16;
    const uint32_t b_sw0 = swz(brn, bhalf * 2), b_sw1 = swz(brn, bhalf * 2 + 1);

    // ldmatrix lane offsets (loop-invariant)
    const int a_r = ((lane >> 3) & 1) * 8 + (lane & 7);
    const int a_c = lane >> 4;
    const int b_r = ((lane >> 4) & 1) * 8 + (lane & 7);
    const int b_c = (lane >> 3) & 1;
    uint32_t offA[2][2], offB[4][2];
    #pragma unroll
    for (int mt = 0; mt < 2; mt++)
        #pragma unroll
        for (int kk = 0; kk < 2; kk++)
            offA[mt][kk] = swz(wm * 32 + mt * 16 + a_r, kk * 2 + a_c);
    #pragma unroll
    for (int j = 0; j < 4; j++)
        #pragma unroll
        for (int kk = 0; kk < 2; kk++)
            offB[j][kk] = swz(wn * 64 + j * 16 + b_r, kk * 2 + b_c);

    float acc[2][8][4];
    #pragma unroll
    for (int i = 0; i < 2; i++)
        #pragma unroll
        for (int j = 0; j < 8; j++)
            #pragma unroll
            for (int q = 0; q < 4; q++) acc[i][j][q] = 0.f;

    float4 la0, la1, lb[4];
    const float4 fz = make_float4(0.f, 0.f, 0.f, 0.f);
    auto load_g = [&](int k0) {
        if (ap) { la0 = *(const float4*)(ap + k0); la1 = *(const float4*)(ap + k0 + 4); }
        else    { la0 = fz; la1 = fz; }
        #pragma unroll
        for (int i = 0; i < 4; i++) lb[i] = *(const float4*)(bp + k0 + i * 4);
    };
    auto store_g = [&](int st) {
        uint4 hi, lo;
        split8(la0, la1, hi, lo);
        *(uint4*)(smem + st + a_sw) = hi;
        *(uint4*)(smem + st + 8192 + a_sw) = lo;
        split8(lb[0], lb[1], hi, lo);
        *(uint4*)(smem + st + 16384 + b_sw0) = hi;
        *(uint4*)(smem + st + 32768 + b_sw0) = lo;
        split8(lb[2], lb[3], hi, lo);
        *(uint4*)(smem + st + 16384 + b_sw1) = hi;
        *(uint4*)(smem + st + 32768 + b_sw1) = lo;
    };
    auto compute = [&](int st) {
        const uint32_t bA = sb + st, bAl = bA + 8192, bB = bA + 16384, bBl = bA + 32768;
        #pragma unroll
        for (int kk = 0; kk < 2; kk++) {
            uint32_t ah[2][4], al_[2][4];
            ldsm4(ah[0],  bA  + offA[0][kk]);
            ldsm4(ah[1],  bA  + offA[1][kk]);
            ldsm4(al_[0], bAl + offA[0][kk]);
            ldsm4(al_[1], bAl + offA[1][kk]);
            #pragma unroll
            for (int j = 0; j < 4; j++) {
                uint32_t bh[4], bl_[4];
                ldsm4(bh,  bB  + offB[j][kk]);
                ldsm4(bl_, bBl + offB[j][kk]);
                #pragma unroll
                for (int mt = 0; mt < 2; mt++) {
                    #pragma unroll
                    for (int nn = 0; nn < 2; nn++) {
                        float* c = acc[mt][j * 2 + nn];
                        mma16816(c, ah[mt],  bh  + 2 * nn);
                        mma16816(c, ah[mt],  bl_ + 2 * nn);
                        mma16816(c, al_[mt], bh  + 2 * nn);
                    }
                }
            }
        }
    };

    load_g(0);
    store_g(0);
    __syncthreads();
    for (int c = 0; c < 64; c++) {
        if (c + 1 < 64) load_g((c + 1) * 32);
        compute((c & 1) * G1_STG);
        if (c + 1 < 64) store_g(((c + 1) & 1) * G1_STG);
        __syncthreads();
    }

    // epilogue: accum -> Cs -> swiglu -> bf16 hi/lo h
    float (*Cs)[256] = (float(*)[256])smem;
    const int cr = wm * 32 + (lane >> 2);
    #pragma unroll
    for (int mt = 0; mt < 2; mt++)
        #pragma unroll
        for (int j = 0; j < 4; j++)
            #pragma unroll
            for (int nn = 0; nn < 2; nn++) {
                float* c = acc[mt][j * 2 + nn];
                const int col = wn * 64 + j * 16 + nn * 8 + (lane & 3) * 2;
                const int r = cr + mt * 16;
                Cs[r][col] = c[0]; Cs[r][col + 1] = c[1];
                Cs[r + 8][col] = c[2]; Cs[r + 8][col + 1] = c[3];
            }
    __syncthreads();
    {
        const int r = tid >> 2;
        const int cb = (tid & 3) * 32;
        uint32_t hw[16], lw[16];
        #pragma unroll
        for (int i = 0; i < 32; i += 2) {
            const float g0 = Cs[r][cb + i],       g1 = Cs[r][cb + i + 1];
            const float u0 = Cs[r][128 + cb + i], u1 = Cs[r][128 + cb + i + 1];
            const float h0 = u0 * g0 / (1.f + __expf(-g0));
            const float h1 = u1 * g1 / (1.f + __expf(-g1));
            const uint32_t b0 = __float_as_uint(h0) & 0xffff0000u;
            const uint32_t b1 = __float_as_uint(h1) & 0xffff0000u;
            hw[i >> 1] = (b0 >> 16) | b1;
            __nv_bfloat162 p = __floats2bfloat162_rn(h0 - __uint_as_float(b0),
                                                     h1 - __uint_as_float(b1));
            lw[i >> 1] = *(uint32_t*)&p;
        }
        __nv_bfloat16* hh = d_h_hi + (size_t)(row0 + r) * F_DIM + f0 + cb;
        __nv_bfloat16* hl = d_h_lo + (size_t)(row0 + r) * F_DIM + f0 + cb;
        #pragma unroll
        for (int q = 0; q < 4; q++) {
            *(uint4*)(hh + q * 8) = *(uint4*)(hw + q * 4);
            *(uint4*)(hl + q * 8) = *(uint4*)(lw + q * 4);
        }
    }
}

// ================ GEMM2 (warp-MMA bf16 3-split): out += wt * (h @ w2^T) ======
// CTA: 128 rows x 128 N-cols, K=768 in 24 chunks of 32.
// 256 thr / 8 warps (4x2), warp tile 32x64.
// stage: A_hi 8K | A_lo 8K | B_hi 8K | B_lo 8K = 32K, x2 = 64K.
#define G2_STG  32768
#define G2_SMEM 65536

__global__ void __launch_bounds__(256, 2)
gemm2_kernel(const float* __restrict__ w2, float* __restrict__ out) {
    const int tile = blockIdx.y;
    if (tile >= d_ntiles) return;
    extern __shared__ __align__(1024) char smem[];
    const int e    = d_tile_expert[tile];
    const int row0 = tile * TM;
    const int n0   = blockIdx.x * 128;
    const int tid  = threadIdx.x;
    const int lane = tid & 31;
    const int warp = tid >> 5;
    const int wm = warp & 3, wn = warp >> 2;
    uint32_t sb;
    asm("{ .reg .u64 t; cvta.to.shared.u64 t, %1; cvt.u32.u64 %0, t; }"
        : "=r"(sb) : "l"(smem));

    const int arow = tid >> 1, ac = (tid & 1) * 2;          // A: 128 rows, 2 chunks ea
    const __nv_bfloat16* aph = d_h_hi + (size_t)(row0 + arow) * F_DIM + ac * 8;
    const __nv_bfloat16* apl = d_h_lo + (size_t)(row0 + arow) * F_DIM + ac * 8;
    const uint32_t a_sw0 = swz(arow, ac), a_sw1 = swz(arow, ac + 1);
    const int brow = tid >> 1, bhalf = tid & 1;             // B: 128 rows, 2 halves ea
    const float* bp = w2 + (size_t)e * D_DIM * F_DIM
                         + (size_t)(n0 + brow) * F_DIM + bhalf * 16;
    const uint32_t b_sw0 = swz(brow, bhalf * 2), b_sw1 = swz(brow, bhalf * 2 + 1);

    const int a_r = ((lane >> 3) & 1) * 8 + (lane & 7);
    const int a_c = lane >> 4;
    const int b_r = ((lane >> 4) & 1) * 8 + (lane & 7);
    const int b_c = (lane >> 3) & 1;
    uint32_t offA[2][2], offB[4][2];
    #pragma unroll
    for (int mt = 0; mt < 2; mt++)
        #pragma unroll
        for (int kk = 0; kk < 2; kk++)
            offA[mt][kk] = swz(wm * 32 + mt * 16 + a_r, kk * 2 + a_c);
    #pragma unroll
    for (int j = 0; j < 4; j++)
        #pragma unroll
        for (int kk = 0; kk < 2; kk++)
            offB[j][kk] = swz(wn * 64 + j * 16 + b_r, kk * 2 + b_c);

    float acc[2][8][4];
    #pragma unroll
    for (int i = 0; i < 2; i++)
        #pragma unroll
        for (int j = 0; j < 8; j++)
            #pragma unroll
            for (int q = 0; q < 4; q++) acc[i][j][q] = 0.f;

    uint4 lah0, lah1, lal0, lal1;
    float4 lb[4];
    auto load_g = [&](int k0) {
        lah0 = *(const uint4*)(aph + k0);
        lah1 = *(const uint4*)(aph + k0 + 8);
        lal0 = *(const uint4*)(apl + k0);
        lal1 = *(const uint4*)(apl + k0 + 8);
        #pragma unroll
        for (int i = 0; i < 4; i++) lb[i] = *(const float4*)(bp + k0 + i * 4);
    };
    auto store_g = [&](int st) {
        *(uint4*)(smem + st + a_sw0) = lah0;
        *(uint4*)(smem + st + a_sw1) = lah1;
        *(uint4*)(smem + st + 8192 + a_sw0) = lal0;
        *(uint4*)(smem + st + 8192 + a_sw1) = lal1;
        uint4 hi, lo;
        split8(lb[0], lb[1], hi, lo);
        *(uint4*)(smem + st + 16384 + b_sw0) = hi;
        *(uint4*)(smem + st + 24576 + b_sw0) = lo;
        split8(lb[2], lb[3], hi, lo);
        *(uint4*)(smem + st + 16384 + b_sw1) = hi;
        *(uint4*)(smem + st + 24576 + b_sw1) = lo;
    };
    auto compute = [&](int st) {
        const uint32_t bA = sb + st, bAl = bA + 8192, bB = bA + 16384, bBl = bA + 24576;
        #pragma unroll
        for (int kk = 0; kk < 2; kk++) {
            uint32_t ah[2][4], al_[2][4];
            ldsm4(ah[0],  bA  + offA[0][kk]);
            ldsm4(ah[1],  bA  + offA[1][kk]);
            ldsm4(al_[0], bAl + offA[0][kk]);
            ldsm4(al_[1], bAl + offA[1][kk]);
            #pragma unroll
            for (int j = 0; j < 4; j++) {
                uint32_t bh[4], bl_[4];
                ldsm4(bh,  bB  + offB[j][kk]);
                ldsm4(bl_, bBl + offB[j][kk]);
                #pragma unroll
                for (int mt = 0; mt < 2; mt++) {
                    #pragma unroll
                    for (int nn = 0; nn < 2; nn++) {
                        float* c = acc[mt][j * 2 + nn];
                        mma16816(c, ah[mt],  bh  + 2 * nn);
                        mma16816(c, ah[mt],  bl_ + 2 * nn);
                        mma16816(c, al_[mt], bh  + 2 * nn);
                    }
                }
            }
        }
    };

    load_g(0);
    store_g(0);
    __syncthreads();
    for (int c = 0; c < 24; c++) {
        if (c + 1 < 24) load_g((c + 1) * 32);
        compute((c & 1) * G2_STG);
        if (c + 1 < 24) store_g(((c + 1) & 1) * G2_STG);
        __syncthreads();
    }

    // epilogue: weighted atomic scatter
    const int cr = wm * 32 + (lane >> 2);
    int prm[4]; float wv[4]; float* op[4];
    #pragma unroll
    for (int q = 0; q < 4; q++) {
        const int rl = cr + (q >> 1) * 16 + (q & 1) * 8;
        const int a = d_perm[row0 + rl];
        prm[q] = a;
        wv[q] = 0.f; op[q] = out;
        if (a >= 0) { wv[q] = d_wt[a]; op[q] = out + (size_t)(a >> 3) * D_DIM + n0; }
    }
    #pragma unroll
    for (int mt = 0; mt < 2; mt++)
        #pragma unroll
        for (int j = 0; j < 4; j++)
            #pragma unroll
            for (int nn = 0; nn < 2; nn++) {
                float* c = acc[mt][j * 2 + nn];
                const int col = wn * 64 + j * 16 + nn * 8 + (lane & 3) * 2;
                const int q0 = mt * 2, q1 = mt * 2 + 1;
                if (prm[q0] >= 0) {
                    atomicAdd(op[q0] + col,     wv[q0] * c[0]);
                    atomicAdd(op[q0] + col + 1, wv[q0] * c[1]);
                }
                if (prm[q1] >= 0) {
                    atomicAdd(op[q1] + col,     wv[q1] * c[2]);
                    atomicAdd(op[q1] + col + 1, wv[q1] * c[3]);
                }
            }
}

// ---------------- launch ----------------
extern "C" void kernel_launch(void* const* d_in, const int* in_sizes, int n_in,
                              void* d_out, int out_size) {
    const float* x    = (const float*)d_in[0];
    const float* gate = (const float*)d_in[1];
    const float* w13  = (const float*)d_in[2];
    const float* w2   = (const float*)d_in[3];
    float* out = (float*)d_out;

    cudaFuncSetAttribute(gemm1_kernel, cudaFuncAttributeMaxDynamicSharedMemorySize, G1_SMEM);
    cudaFuncSetAttribute(gemm2_kernel, cudaFuncAttributeMaxDynamicSharedMemorySize, G2_SMEM);

    cudaMemsetAsync(d_out, 0, (size_t)T_TOK * D_DIM * sizeof(float));
    zero_counts_kernel<<<1, E_NUM>>>();
    router_kernel<<<T_TOK, 256>>>(x, gate);
    build_kernel<<<1, 256>>>();
    scatter_kernel<<<NA / 256, 256>>>();
    gemm1_kernel<<<dim3(F_DIM / 128, MAX_TILES), 512, G1_SMEM>>>(x, w13);
    gemm2_kernel<<<dim3(D_DIM / 128, MAX_TILES), 256, G2_SMEM>>>(w2, out);
}

// round 13
// speedup vs baseline: 3.2883x; 1.3082x over previous
#include <cuda_runtime.h>
#include <cuda_fp16.h>
#include <math.h>
#include <stdint.h>

// ---------------- problem constants ----------------
#define T_TOK 1024
#define D_DIM 2048
#define E_NUM 64
#define F_DIM 768
#define TOPK  8
#define NA    (T_TOK * TOPK)
#define TM    128
#define MAX_ROWS  16384           // >= 8192 + 64*127 = 16320
#define MAX_TILES 128

// ---------------- device scratch ----------------
__device__ int   d_counts[E_NUM];
__device__ int   d_cursor[E_NUM];
__device__ int   d_tile_expert[MAX_TILES];
__device__ int   d_ntiles;
__device__ int   d_perm[MAX_ROWS];
__device__ int   d_topk[NA];
__device__ float d_wt[NA];
__device__ __align__(16) __half d_h_hi[(size_t)MAX_ROWS * F_DIM];
__device__ __align__(16) __half d_h_lo[(size_t)MAX_ROWS * F_DIM];

// ---------------- warp-MMA helpers (base sm_103 ISA) ----------------
// smem tiles: rows of 32 halfs (64B) = 4 chunks of 16B.
// swizzle: phys chunk = c ^ ((row>>1)&3)  -> conflict-free ldmatrix & STS.128
__device__ __forceinline__ uint32_t swz(int row, int c) {
    return (uint32_t)(row * 64 + ((c ^ ((row >> 1) & 3)) << 4));
}
__device__ __forceinline__ void ldsm4(uint32_t* r, uint32_t addr) {
    asm volatile("ldmatrix.sync.aligned.m8n8.x4.shared.b16 {%0,%1,%2,%3}, [%4];"
                 : "=r"(r[0]), "=r"(r[1]), "=r"(r[2]), "=r"(r[3]) : "r"(addr));
}
__device__ __forceinline__ void mma16816(float* c, const uint32_t* a, const uint32_t* b) {
    asm volatile(
        "mma.sync.aligned.m16n8k16.row.col.f32.f16.f16.f32 "
        "{%0,%1,%2,%3}, {%4,%5,%6,%7}, {%8,%9}, {%0,%1,%2,%3};"
        : "+f"(c[0]), "+f"(c[1]), "+f"(c[2]), "+f"(c[3])
        : "r"(a[0]), "r"(a[1]), "r"(a[2]), "r"(a[3]), "r"(b[0]), "r"(b[1]));
}
// fp32x8 -> fp16 hi (rn) + fp16 lo (rn residual)
__device__ __forceinline__ void split8h(float4 v0, float4 v1, uint4& hi, uint4& lo) {
    float f[8] = {v0.x, v0.y, v0.z, v0.w, v1.x, v1.y, v1.z, v1.w};
    uint32_t hp[4], lp[4];
    #pragma unroll
    for (int i = 0; i < 4; i++) {
        const __half h0 = __float2half_rn(f[2 * i]);
        const __half h1 = __float2half_rn(f[2 * i + 1]);
        __half2 hh = __halves2half2(h0, h1);
        hp[i] = *(uint32_t*)&hh;
        const float r0 = f[2 * i]     - __half2float(h0);
        const float r1 = f[2 * i + 1] - __half2float(h1);
        __half2 ll = __floats2half2_rn(r0, r1);
        lp[i] = *(uint32_t*)&ll;
    }
    hi.x = hp[0]; hi.y = hp[1]; hi.z = hp[2]; hi.w = hp[3];
    lo.x = lp[0]; lo.y = lp[1]; lo.z = lp[2]; lo.w = lp[3];
}
// fp32x8 -> fp16 (rn), hi only
__device__ __forceinline__ uint4 cvt8h(float4 a, float4 b) {
    uint4 o; __half2 p;
    p = __floats2half2_rn(a.x, a.y); o.x = *(uint32_t*)&p;
    p = __floats2half2_rn(a.z, a.w); o.y = *(uint32_t*)&p;
    p = __floats2half2_rn(b.x, b.y); o.z = *(uint32_t*)&p;
    p = __floats2half2_rn(b.z, b.w); o.w = *(uint32_t*)&p;
    return o;
}

// ---------------- k0..k3: routing ----------------
__global__ void zero_counts_kernel() { d_counts[threadIdx.x] = 0; }

__global__ void router_kernel(const float* __restrict__ x,
                              const float* __restrict__ gate) {
    __shared__ float xs[D_DIM];
    __shared__ float slog[E_NUM];
    const int t = blockIdx.x;
    const int tid = threadIdx.x;
    const float4* xg = (const float4*)(x + (size_t)t * D_DIM);
    float4* xs4 = (float4*)xs;
    xs4[tid] = xg[tid];
    xs4[tid + 256] = xg[tid + 256];
    __syncthreads();
    const int e = tid >> 2, sub = tid & 3;
    const float4* g4 = (const float4*)(gate + (size_t)e * D_DIM);
    float p = 0.f;
    #pragma unroll 4
    for (int j = sub; j < D_DIM / 4; j += 4) {
        float4 xv = xs4[j], gv = g4[j];
        p += xv.x * gv.x + xv.y * gv.y + xv.z * gv.z + xv.w * gv.w;
    }
    p += __shfl_down_sync(0xffffffffu, p, 2, 4);
    p += __shfl_down_sync(0xffffffffu, p, 1, 4);
    if (sub == 0) slog[e] = p;
    __syncthreads();
    if (tid == 0) {
        float l[E_NUM];
        #pragma unroll
        for (int i = 0; i < E_NUM; i++) l[i] = slog[i];
        int idx[TOPK]; float val[TOPK];
        for (int k = 0; k < TOPK; k++) {
            int bi = 0; float bv = -1e30f;
            for (int i = 0; i < E_NUM; i++)
                if (l[i] > bv) { bv = l[i]; bi = i; }
            idx[k] = bi; val[k] = bv; l[bi] = -1e30f;
        }
        const float m = val[0];
        float w[TOPK], s = 0.f;
        for (int k = 0; k < TOPK; k++) { w[k] = __expf(val[k] - m); s += w[k]; }
        const float inv = 1.f / s;
        for (int k = 0; k < TOPK; k++) {
            d_topk[t * TOPK + k] = idx[k];
            d_wt  [t * TOPK + k] = w[k] * inv;
            atomicAdd(&d_counts[idx[k]], 1);
        }
    }
}

__global__ void build_kernel() {
    const int tid = threadIdx.x;
    if (tid == 0) {
        int off = 0;
        for (int e = 0; e < E_NUM; e++) {
            d_cursor[e] = off;
            const int nt = (d_counts[e] + TM - 1) / TM;
            for (int j = 0; j < nt; j++) d_tile_expert[off / TM + j] = e;
            off += nt * TM;
        }
        d_ntiles = off / TM;
    }
    for (int i = tid; i < MAX_ROWS; i += blockDim.x) d_perm[i] = -1;
}

__global__ void scatter_kernel() {
    const int i = blockIdx.x * blockDim.x + threadIdx.x;
    if (i < NA) {
        const int e = d_topk[i];
        const int pos = atomicAdd(&d_cursor[e], 1);
        d_perm[pos] = i;
    }
}

// ================ GEMM1 + fused SwiGLU (fp16 2-term split) ===================
// CTA: 128 rows x (gate 128 | up 128), K=2048 in 64 chunks of 32.
// 512 thr / 16 warps (4x4), warp tile 32x64.
// stage: A_hi 8K | A_lo 8K | B_hi 16K = 32K, x2 = 64K; epilogue Cs 128K.
#define G1_STG  32768
#define G1_SMEM 131072

__global__ void __launch_bounds__(512, 1)
gemm1_kernel(const float* __restrict__ x, const float* __restrict__ w13) {
    const int tile = blockIdx.y;
    if (tile >= d_ntiles) return;
    extern __shared__ __align__(1024) char smem[];
    const int e    = d_tile_expert[tile];
    const int row0 = tile * TM;
    const int f0   = blockIdx.x * 128;
    const int tid  = threadIdx.x;
    const int lane = tid & 31;
    const int warp = tid >> 5;
    const int wm = warp & 3, wn = warp >> 2;
    uint32_t sb;
    asm("{ .reg .u64 t; cvta.to.shared.u64 t, %1; cvt.u32.u64 %0, t; }"
        : "=r"(sb) : "l"(smem));

    const int ar = tid >> 2, aseg = tid & 3;                // A: 128 rows x 4 chunks
    const int aidx = d_perm[row0 + ar];
    const float* ap = (aidx >= 0) ? (x + (size_t)(aidx >> 3) * D_DIM + aseg * 8) : nullptr;
    const uint32_t a_sw = swz(ar, aseg);
    const int brn = tid >> 1, bhalf = tid & 1;              // B: 256 rows x 2 halves
    const int brow = (brn < 128) ? (f0 + brn) : (F_DIM + f0 + brn - 128);
    const float* bp = w13 + (size_t)e * (2 * F_DIM) * D_DIM
                          + (size_t)brow * D_DIM + bhalf * 16;
    const uint32_t b_sw0 = swz(brn, bhalf * 2), b_sw1 = swz(brn, bhalf * 2 + 1);

    const int a_r = ((lane >> 3) & 1) * 8 + (lane & 7);
    const int a_c = lane >> 4;
    const int b_r = ((lane >> 4) & 1) * 8 + (lane & 7);
    const int b_c = (lane >> 3) & 1;
    uint32_t offA[2][2], offB[4][2];
    #pragma unroll
    for (int mt = 0; mt < 2; mt++)
        #pragma unroll
        for (int kk = 0; kk < 2; kk++)
            offA[mt][kk] = swz(wm * 32 + mt * 16 + a_r, kk * 2 + a_c);
    #pragma unroll
    for (int j = 0; j < 4; j++)
        #pragma unroll
        for (int kk = 0; kk < 2; kk++)
            offB[j][kk] = swz(wn * 64 + j * 16 + b_r, kk * 2 + b_c);

    float acc[2][8][4];
    #pragma unroll
    for (int i = 0; i < 2; i++)
        #pragma unroll
        for (int j = 0; j < 8; j++)
            #pragma unroll
            for (int q = 0; q < 4; q++) acc[i][j][q] = 0.f;

    float4 la0, la1, lb[4];
    const float4 fz = make_float4(0.f, 0.f, 0.f, 0.f);
    auto load_g = [&](int k0) {
        if (ap) { la0 = *(const float4*)(ap + k0); la1 = *(const float4*)(ap + k0 + 4); }
        else    { la0 = fz; la1 = fz; }
        #pragma unroll
        for (int i = 0; i < 4; i++) lb[i] = *(const float4*)(bp + k0 + i * 4);
    };
    auto store_g = [&](int st) {
        uint4 hi, lo;
        split8h(la0, la1, hi, lo);
        *(uint4*)(smem + st + a_sw) = hi;
        *(uint4*)(smem + st + 8192 + a_sw) = lo;
        *(uint4*)(smem + st + 16384 + b_sw0) = cvt8h(lb[0], lb[1]);
        *(uint4*)(smem + st + 16384 + b_sw1) = cvt8h(lb[2], lb[3]);
    };
    auto compute = [&](int st) {
        const uint32_t bA = sb + st, bAl = bA + 8192, bB = bA + 16384;
        #pragma unroll
        for (int kk = 0; kk < 2; kk++) {
            uint32_t ah[2][4], al_[2][4];
            ldsm4(ah[0],  bA  + offA[0][kk]);
            ldsm4(ah[1],  bA  + offA[1][kk]);
            ldsm4(al_[0], bAl + offA[0][kk]);
            ldsm4(al_[1], bAl + offA[1][kk]);
            #pragma unroll
            for (int j = 0; j < 4; j++) {
                uint32_t bh[4];
                ldsm4(bh, bB + offB[j][kk]);
                #pragma unroll
                for (int mt = 0; mt < 2; mt++) {
                    #pragma unroll
                    for (int nn = 0; nn < 2; nn++) {
                        float* c = acc[mt][j * 2 + nn];
                        mma16816(c, ah[mt],  bh + 2 * nn);
                        mma16816(c, al_[mt], bh + 2 * nn);
                    }
                }
            }
        }
    };

    load_g(0);
    store_g(0);
    __syncthreads();
    for (int c = 0; c < 64; c++) {
        if (c + 1 < 64) load_g((c + 1) * 32);
        compute((c & 1) * G1_STG);
        if (c + 1 < 64) store_g(((c + 1) & 1) * G1_STG);
        __syncthreads();
    }

    // epilogue: accum -> Cs -> swiglu -> fp16 hi/lo h
    float (*Cs)[256] = (float(*)[256])smem;
    const int cr = wm * 32 + (lane >> 2);
    #pragma unroll
    for (int mt = 0; mt < 2; mt++)
        #pragma unroll
        for (int j = 0; j < 4; j++)
            #pragma unroll
            for (int nn = 0; nn < 2; nn++) {
                float* c = acc[mt][j * 2 + nn];
                const int col = wn * 64 + j * 16 + nn * 8 + (lane & 3) * 2;
                const int r = cr + mt * 16;
                Cs[r][col] = c[0]; Cs[r][col + 1] = c[1];
                Cs[r + 8][col] = c[2]; Cs[r + 8][col + 1] = c[3];
            }
    __syncthreads();
    {
        const int r = tid >> 2;
        const int cb = (tid & 3) * 32;
        uint32_t hw[16], lw[16];
        #pragma unroll
        for (int i = 0; i < 32; i += 2) {
            const float g0 = Cs[r][cb + i],       g1 = Cs[r][cb + i + 1];
            const float u0 = Cs[r][128 + cb + i], u1 = Cs[r][128 + cb + i + 1];
            const float h0 = u0 * g0 / (1.f + __expf(-g0));
            const float h1 = u1 * g1 / (1.f + __expf(-g1));
            const __half q0 = __float2half_rn(h0);
            const __half q1 = __float2half_rn(h1);
            __half2 hp = __halves2half2(q0, q1);
            hw[i >> 1] = *(uint32_t*)&hp;
            __half2 lp = __floats2half2_rn(h0 - __half2float(q0),
                                           h1 - __half2float(q1));
            lw[i >> 1] = *(uint32_t*)&lp;
        }
        __half* hh = d_h_hi + (size_t)(row0 + r) * F_DIM + f0 + cb;
        __half* hl = d_h_lo + (size_t)(row0 + r) * F_DIM + f0 + cb;
        #pragma unroll
        for (int q = 0; q < 4; q++) {
            *(uint4*)(hh + q * 8) = *(uint4*)(hw + q * 4);
            *(uint4*)(hl + q * 8) = *(uint4*)(lw + q * 4);
        }
    }
}

// ================ GEMM2 (fp16 2-term split): out += wt * (h @ w2^T) ==========
// CTA: 128 rows x 128 N-cols, K=768 in 24 chunks of 32.
// 256 thr / 8 warps (4x2), warp tile 32x64.
// stage: A_hi 8K | A_lo 8K | B_hi 8K = 24K, x2 = 48K. occupancy 2.
#define G2_STG  24576
#define G2_SMEM 49152

__global__ void __launch_bounds__(256, 2)
gemm2_kernel(const float* __restrict__ w2, float* __restrict__ out) {
    const int tile = blockIdx.y;
    if (tile >= d_ntiles) return;
    extern __shared__ __align__(1024) char smem[];
    const int e    = d_tile_expert[tile];
    const int row0 = tile * TM;
    const int n0   = blockIdx.x * 128;
    const int tid  = threadIdx.x;
    const int lane = tid & 31;
    const int warp = tid >> 5;
    const int wm = warp & 3, wn = warp >> 2;
    uint32_t sb;
    asm("{ .reg .u64 t; cvta.to.shared.u64 t, %1; cvt.u32.u64 %0, t; }"
        : "=r"(sb) : "l"(smem));

    const int arow = tid >> 1, ac = (tid & 1) * 2;          // A: 128 rows, 2 chunks ea
    const __half* aph = d_h_hi + (size_t)(row0 + arow) * F_DIM + ac * 8;
    const __half* apl = d_h_lo + (size_t)(row0 + arow) * F_DIM + ac * 8;
    const uint32_t a_sw0 = swz(arow, ac), a_sw1 = swz(arow, ac + 1);
    const int brow = tid >> 1, bhalf = tid & 1;             // B: 128 rows, 2 halves ea
    const float* bp = w2 + (size_t)e * D_DIM * F_DIM
                         + (size_t)(n0 + brow) * F_DIM + bhalf * 16;
    const uint32_t b_sw0 = swz(brow, bhalf * 2), b_sw1 = swz(brow, bhalf * 2 + 1);

    const int a_r = ((lane >> 3) & 1) * 8 + (lane & 7);
    const int a_c = lane >> 4;
    const int b_r = ((lane >> 4) & 1) * 8 + (lane & 7);
    const int b_c = (lane >> 3) & 1;
    uint32_t offA[2][2], offB[4][2];
    #pragma unroll
    for (int mt = 0; mt < 2; mt++)
        #pragma unroll
        for (int kk = 0; kk < 2; kk++)
            offA[mt][kk] = swz(wm * 32 + mt * 16 + a_r, kk * 2 + a_c);
    #pragma unroll
    for (int j = 0; j < 4; j++)
        #pragma unroll
        for (int kk = 0; kk < 2; kk++)
            offB[j][kk] = swz(wn * 64 + j * 16 + b_r, kk * 2 + b_c);

    float acc[2][8][4];
    #pragma unroll
    for (int i = 0; i < 2; i++)
        #pragma unroll
        for (int j = 0; j < 8; j++)
            #pragma unroll
            for (int q = 0; q < 4; q++) acc[i][j][q] = 0.f;

    uint4 lah0, lah1, lal0, lal1;
    float4 lb[4];
    auto load_g = [&](int k0) {
        lah0 = *(const uint4*)(aph + k0);
        lah1 = *(const uint4*)(aph + k0 + 8);
        lal0 = *(const uint4*)(apl + k0);
        lal1 = *(const uint4*)(apl + k0 + 8);
        #pragma unroll
        for (int i = 0; i < 4; i++) lb[i] = *(const float4*)(bp + k0 + i * 4);
    };
    auto store_g = [&](int st) {
        *(uint4*)(smem + st + a_sw0) = lah0;
        *(uint4*)(smem + st + a_sw1) = lah1;
        *(uint4*)(smem + st + 8192 + a_sw0) = lal0;
        *(uint4*)(smem + st + 8192 + a_sw1) = lal1;
        *(uint4*)(smem + st + 16384 + b_sw0) = cvt8h(lb[0], lb[1]);
        *(uint4*)(smem + st + 16384 + b_sw1) = cvt8h(lb[2], lb[3]);
    };
    auto compute = [&](int st) {
        const uint32_t bA = sb + st, bAl = bA + 8192, bB = bA + 16384;
        #pragma unroll
        for (int kk = 0; kk < 2; kk++) {
            uint32_t ah[2][4], al_[2][4];
            ldsm4(ah[0],  bA  + offA[0][kk]);
            ldsm4(ah[1],  bA  + offA[1][kk]);
            ldsm4(al_[0], bAl + offA[0][kk]);
            ldsm4(al_[1], bAl + offA[1][kk]);
            #pragma unroll
            for (int j = 0; j < 4; j++) {
                uint32_t bh[4];
                ldsm4(bh, bB + offB[j][kk]);
                #pragma unroll
                for (int mt = 0; mt < 2; mt++) {
                    #pragma unroll
                    for (int nn = 0; nn < 2; nn++) {
                        float* c = acc[mt][j * 2 + nn];
                        mma16816(c, ah[mt],  bh + 2 * nn);
                        mma16816(c, al_[mt], bh + 2 * nn);
                    }
                }
            }
        }
    };

    load_g(0);
    store_g(0);
    __syncthreads();
    for (int c = 0; c < 24; c++) {
        if (c + 1 < 24) load_g((c + 1) * 32);
        compute((c & 1) * G2_STG);
        if (c + 1 < 24) store_g(((c + 1) & 1) * G2_STG);
        __syncthreads();
    }

    // epilogue: weighted atomic scatter
    const int cr = wm * 32 + (lane >> 2);
    int prm[4]; float wv[4]; float* op[4];
    #pragma unroll
    for (int q = 0; q < 4; q++) {
        const int rl = cr + (q >> 1) * 16 + (q & 1) * 8;
        const int a = d_perm[row0 + rl];
        prm[q] = a;
        wv[q] = 0.f; op[q] = out;
        if (a >= 0) { wv[q] = d_wt[a]; op[q] = out + (size_t)(a >> 3) * D_DIM + n0; }
    }
    #pragma unroll
    for (int mt = 0; mt < 2; mt++)
        #pragma unroll
        for (int j = 0; j < 4; j++)
            #pragma unroll
            for (int nn = 0; nn < 2; nn++) {
                float* c = acc[mt][j * 2 + nn];
                const int col = wn * 64 + j * 16 + nn * 8 + (lane & 3) * 2;
                const int q0 = mt * 2, q1 = mt * 2 + 1;
                if (prm[q0] >= 0) {
                    atomicAdd(op[q0] + col,     wv[q0] * c[0]);
                    atomicAdd(op[q0] + col + 1, wv[q0] * c[1]);
                }
                if (prm[q1] >= 0) {
                    atomicAdd(op[q1] + col,     wv[q1] * c[2]);
                    atomicAdd(op[q1] + col + 1, wv[q1] * c[3]);
                }
            }
}

// ---------------- launch ----------------
extern "C" void kernel_launch(void* const* d_in, const int* in_sizes, int n_in,
                              void* d_out, int out_size) {
    const float* x    = (const float*)d_in[0];
    const float* gate = (const float*)d_in[1];
    const float* w13  = (const float*)d_in[2];
    const float* w2   = (const float*)d_in[3];
    float* out = (float*)d_out;

    cudaFuncSetAttribute(gemm1_kernel, cudaFuncAttributeMaxDynamicSharedMemorySize, G1_SMEM);
    cudaFuncSetAttribute(gemm2_kernel, cudaFuncAttributeMaxDynamicSharedMemorySize, G2_SMEM);

    cudaMemsetAsync(d_out, 0, (size_t)T_TOK * D_DIM * sizeof(float));
    zero_counts_kernel<<<1, E_NUM>>>();
    router_kernel<<<T_TOK, 256>>>(x, gate);
    build_kernel<<<1, 256>>>();
    scatter_kernel<<<NA / 256, 256>>>();
    gemm1_kernel<<<dim3(F_DIM / 128, MAX_TILES), 512, G1_SMEM>>>(x, w13);
    gemm2_kernel<<<dim3(D_DIM / 128, MAX_TILES), 256, G2_SMEM>>>(w2, out);
}